// round 6
// baseline (speedup 1.0000x reference)
#include <cuda_runtime.h>
#include <cuda_bf16.h>

// B=8, L=4000, D=512, WINDOW=5.
// Identity: shift/unshift cancel -> per column c, sort consecutive 5-row
// windows whose start rows are ≡ c (mod 5), circular over L.
//
// R6: register-resident kernel (R5) + PIPE REBALANCING. The alu pipe
// (SEL/FMNMX) was a co-binder at 47.5% while fma sat idle at 1.8%.
// The up-shift's 65 selects are re-expressed as r = y + p*(x-y)
// (FADD+FFMA, fma pipe), cutting the alu-pipe floor ~240 -> ~175 instrs
// per thread while loading the idle fma pipe (~160).

#define LROWS 4000
#define DCOLS 512
#define TROWS 20
#define NREG  (TROWS + 9)      // 29
#define NTHREADS 256

#define CE(x, y) { float _lo = fminf(x, y); float _hi = fmaxf(x, y); x = _lo; y = _hi; }

__global__ __launch_bounds__(NTHREADS, 5)
void swd_reg_kernel(const float* __restrict__ v, float* __restrict__ out) {
    const int lane   = threadIdx.x & 31;
    const int warpid = threadIdx.x >> 5;          // 0..7
    const int rt     = blockIdx.x >> 1;           // row tile 0..199
    const int half   = blockIdx.x & 1;            // 0..1
    const int b      = blockIdx.y;                // batch 0..7
    const int cg     = half * 8 + warpid;         // column group 0..15
    const int c      = cg * 32 + lane;            // column 0..511
    const int P      = rt * TROWS;                // first output row

    float a[NREG];

    // ---- Load rows [P-4, P+25) of column c, coalesced across the warp ----
    if (P >= 4 && P + NREG - 4 <= LROWS) {
        const float* __restrict__ vp =
            v + ((size_t)b * LROWS + (P - 4)) * DCOLS + c;
        #pragma unroll
        for (int j = 0; j < NREG; j++) a[j] = vp[j * DCOLS];
    } else {
        const float* __restrict__ vb = v + (size_t)b * LROWS * DCOLS + c;
        #pragma unroll
        for (int j = 0; j < NREG; j++) {
            int gr = P - 4 + j;
            if (gr < 0)           gr += LROWS;
            else if (gr >= LROWS) gr -= LROWS;
            a[j] = vb[(size_t)gr * DCOLS];
        }
    }

    // ---- Phase: first window start in frame is local index o=(c+4)%5 ----
    const int o  = (c + 4) % 5;
    const bool o1 = (o & 1) != 0;
    const bool o2 = (o & 2) != 0;
    const bool o4 = (o & 4) != 0;
    // fp predicates for the fma-pipe selects
    const float p1 = o1 ? 1.0f : 0.0f;
    const float p2 = o2 ? 1.0f : 0.0f;
    const float p4 = o4 ? 1.0f : 0.0f;

    // ---- Barrel shift DOWN by o (alu-pipe SELs): a[j] <- orig[j+o] ----
    #pragma unroll
    for (int j = 0; j < NREG - 1; j++) a[j] = o1 ? a[j + 1] : a[j];
    #pragma unroll
    for (int j = 0; j < NREG - 2; j++) a[j] = o2 ? a[j + 2] : a[j];
    #pragma unroll
    for (int j = 0; j < NREG - 4; j++) a[j] = o4 ? a[j + 4] : a[j];

    // ---- Sort 5 windows at static offsets 0,5,10,15,20 (9-comparator net) ----
    #pragma unroll
    for (int m = 0; m < 5; m++) {
        float a0 = a[5*m+0], a1 = a[5*m+1], a2 = a[5*m+2],
              a3 = a[5*m+3], a4 = a[5*m+4];
        CE(a0, a1); CE(a3, a4); CE(a2, a4);
        CE(a2, a3); CE(a0, a3); CE(a0, a2);
        CE(a1, a4); CE(a1, a3); CE(a1, a2);
        a[5*m+0] = a0; a[5*m+1] = a1; a[5*m+2] = a2;
        a[5*m+3] = a3; a[5*m+4] = a4;
    }

    // ---- Barrel shift UP by o on the FMA PIPE: a[i] <- sorted[i-o] ----
    // select(p, x, y) = y + p*(x - y), p in {0,1}: FADD + FFMA (fma pipe).
    // Exact for p=0; <=~2ulp for p=1 (well under the 1e-3 threshold).
    // Descending; stage lower bound = its shift amount (R5 bounds fix).
    #pragma unroll
    for (int i = TROWS + 3; i >= 4; i--) {
        float d = a[i - 4] - a[i];
        a[i] = fmaf(p4, d, a[i]);
    }
    #pragma unroll
    for (int i = TROWS + 3; i >= 2; i--) {
        float d = a[i - 2] - a[i];
        a[i] = fmaf(p2, d, a[i]);
    }
    #pragma unroll
    for (int i = TROWS + 3; i >= 1; i--) {
        float d = a[i - 1] - a[i];
        a[i] = fmaf(p1, d, a[i]);
    }

    // ---- Store output rows [P, P+20), coalesced across the warp ----
    float* __restrict__ op = out + ((size_t)b * LROWS + P) * DCOLS + c;
    #pragma unroll
    for (int d = 0; d < TROWS; d++) op[d * DCOLS] = a[d + 4];
}

extern "C" void kernel_launch(void* const* d_in, const int* in_sizes, int n_in,
                              void* d_out, int out_size) {
    const float* v = (const float*)d_in[2];   // inputs: q (unused), k (unused), v
    float* out     = (float*)d_out;

    dim3 grid((LROWS / TROWS) * 2, 8);        // 400 x 8 = 3200 blocks, 256 thr
    swd_reg_kernel<<<grid, NTHREADS>>>(v, out);
}

// round 7
// speedup vs baseline: 1.0514x; 1.0514x over previous
#include <cuda_runtime.h>
#include <cuda_bf16.h>

// B=8, L=4000, D=512, WINDOW=5.
// Identity: shift/unshift cancel -> per column c, sort consecutive 5-row
// windows whose start rows are ≡ c (mod 5), circular over L.
//
// R7: register-resident kernel with SMALL FRAME for occupancy. R6 had every
// pipe <52% (latency-bound) with occ capped at 62.5% by 46 regs. TROWS=10
// (NREG=19) cuts the frame to ~32-36 regs -> 7-8 CTAs/SM (87-100% occ),
// halves the per-warp serial chain, and doubles CTA count (6400) for a
// smaller tail. Halo re-reads (1.9x) are L2 hits; DRAM traffic unchanged.

#define LROWS 4000
#define DCOLS 512
#define TROWS 10
#define NREG  (TROWS + 9)      // 19
#define NTHREADS 256

#define CE(x, y) { float _lo = fminf(x, y); float _hi = fmaxf(x, y); x = _lo; y = _hi; }

__global__ __launch_bounds__(NTHREADS, 7)
void swd_reg_kernel(const float* __restrict__ v, float* __restrict__ out) {
    const int lane   = threadIdx.x & 31;
    const int warpid = threadIdx.x >> 5;          // 0..7
    const int rt     = blockIdx.x >> 1;           // row tile 0..399
    const int half   = blockIdx.x & 1;            // 0..1
    const int b      = blockIdx.y;                // batch 0..7
    const int c      = (half * 8 + warpid) * 32 + lane;  // column 0..511
    const int P      = rt * TROWS;                // first output row

    float a[NREG];

    // ---- Load rows [P-4, P+15) of column c, coalesced across the warp ----
    if (P >= 4 && P + NREG - 4 <= LROWS) {
        const float* __restrict__ vp =
            v + ((size_t)b * LROWS + (P - 4)) * DCOLS + c;
        #pragma unroll
        for (int j = 0; j < NREG; j++) a[j] = vp[j * DCOLS];
    } else {
        const float* __restrict__ vb = v + (size_t)b * LROWS * DCOLS + c;
        #pragma unroll
        for (int j = 0; j < NREG; j++) {
            int gr = P - 4 + j;
            if (gr < 0)           gr += LROWS;
            else if (gr >= LROWS) gr -= LROWS;
            a[j] = vb[(size_t)gr * DCOLS];
        }
    }

    // ---- Phase: first window start in frame is local index o=(c+4)%5 ----
    const int o  = (c + 4) % 5;
    const bool o1 = (o & 1) != 0;
    const bool o2 = (o & 2) != 0;
    const bool o4 = (o & 4) != 0;
    const float p1 = o1 ? 1.0f : 0.0f;
    const float p2 = o2 ? 1.0f : 0.0f;
    const float p4 = o4 ? 1.0f : 0.0f;

    // ---- Barrel shift DOWN by o (alu SELs): a[j] <- orig[j+o], j<=14 ----
    #pragma unroll
    for (int j = 0; j < NREG - 1; j++) a[j] = o1 ? a[j + 1] : a[j];
    #pragma unroll
    for (int j = 0; j < NREG - 2; j++) a[j] = o2 ? a[j + 2] : a[j];
    #pragma unroll
    for (int j = 0; j < NREG - 4; j++) a[j] = o4 ? a[j + 4] : a[j];

    // ---- Sort 3 windows at static offsets 0,5,10 (9-comparator network) ----
    #pragma unroll
    for (int m = 0; m < 3; m++) {
        float a0 = a[5*m+0], a1 = a[5*m+1], a2 = a[5*m+2],
              a3 = a[5*m+3], a4 = a[5*m+4];
        CE(a0, a1); CE(a3, a4); CE(a2, a4);
        CE(a2, a3); CE(a0, a3); CE(a0, a2);
        CE(a1, a4); CE(a1, a3); CE(a1, a2);
        a[5*m+0] = a0; a[5*m+1] = a1; a[5*m+2] = a2;
        a[5*m+3] = a3; a[5*m+4] = a4;
    }

    // ---- Barrel shift UP by o on the fma pipe: a[i] <- sorted[i-o] ----
    // select(p,x,y) = y + p*(x-y); exact for p=0, <=~2ulp for p=1.
    // Descending; stage lower bound = its own shift amount (R5 fix).
    #pragma unroll
    for (int i = TROWS + 3; i >= 4; i--) {
        float d = a[i - 4] - a[i];
        a[i] = fmaf(p4, d, a[i]);
    }
    #pragma unroll
    for (int i = TROWS + 3; i >= 2; i--) {
        float d = a[i - 2] - a[i];
        a[i] = fmaf(p2, d, a[i]);
    }
    #pragma unroll
    for (int i = TROWS + 3; i >= 1; i--) {
        float d = a[i - 1] - a[i];
        a[i] = fmaf(p1, d, a[i]);
    }

    // ---- Store output rows [P, P+10), coalesced across the warp ----
    float* __restrict__ op = out + ((size_t)b * LROWS + P) * DCOLS + c;
    #pragma unroll
    for (int d = 0; d < TROWS; d++) op[d * DCOLS] = a[d + 4];
}

extern "C" void kernel_launch(void* const* d_in, const int* in_sizes, int n_in,
                              void* d_out, int out_size) {
    const float* v = (const float*)d_in[2];   // inputs: q (unused), k (unused), v
    float* out     = (float*)d_out;

    dim3 grid((LROWS / TROWS) * 2, 8);        // 800 x 8 = 6400 blocks, 256 thr
    swd_reg_kernel<<<grid, NTHREADS>>>(v, out);
}

// round 8
// speedup vs baseline: 1.1378x; 1.0822x over previous
#include <cuda_runtime.h>
#include <cuda_bf16.h>
#include <cstdint>

// B=8, L=4000, D=512, WINDOW=5.
// Identity: shift/unshift cancel -> per column c, sort consecutive 5-row
// windows whose start rows are ≡ c (mod 5), circular over L.
//
// R8: bulk-async design. A CTA's input frame (19 full rows) and output tile
// (10 full rows) are CONTIGUOUS in global memory, so cp.async.bulk (UBLKCP)
// moves them wholesale: no LDG/STG/fill/flush passes. Threads sort windows
// in smem at per-lane address offsets (no register barrel shifts at all):
// 3 windows x (5 LDS + 9 FMNMX + 5 STS) = ~4.3 instr/output, conflict-free
// banks. smem 38.9KB -> 4 CTAs/SM, 100% occupancy. DRAM becomes the binder.

#define LROWS 4000
#define DCOLS 512
#define ROWBYTES (DCOLS * 4)       // 2048
#define TROWS 10
#define SROWS (TROWS + 9)          // 19
#define NTHREADS 512
#define FRAME_BYTES (SROWS * ROWBYTES)   // 38912
#define OUT_BYTES   (TROWS * ROWBYTES)   // 20480
#define SMEM_BYTES  (FRAME_BYTES + 16)   // + mbarrier

#define CE(x, y) { float _lo = fminf(x, y); float _hi = fmaxf(x, y); x = _lo; y = _hi; }

__global__ __launch_bounds__(NTHREADS, 4)
void swd_bulk_kernel(const float* __restrict__ v, float* __restrict__ out) {
    extern __shared__ float sm[];                    // [SROWS][DCOLS] + mbar
    uint32_t smem_base;
    asm("{ .reg .u64 t; cvta.to.shared.u64 t, %1; cvt.u32.u64 %0, t; }"
        : "=r"(smem_base) : "l"(sm));
    const uint32_t mbar = smem_base + FRAME_BYTES;   // 8-aligned

    const int tx   = threadIdx.x;                    // column 0..511
    const int tile = blockIdx.x;                     // 0..399
    const int b    = blockIdx.y;                     // 0..7
    const int P    = tile * TROWS;                   // first output row

    const float* __restrict__ vb = v   + (size_t)b * LROWS * DCOLS;
    float*       __restrict__ ob = out + (size_t)b * LROWS * DCOLS;

    // ---- mbarrier init (tx 0), then make visible ----
    if (tx == 0) {
        asm volatile("mbarrier.init.shared.b64 [%0], 1;" :: "r"(mbar) : "memory");
    }
    __syncthreads();

    // ---- Bulk-async load of rows [P-4, P+15) (circular; <=2 segments) ----
    if (tx == 0) {
        asm volatile("mbarrier.arrive.expect_tx.shared.b64 _, [%0], %1;"
                     :: "r"(mbar), "r"((uint32_t)FRAME_BYTES) : "memory");
        int gr0 = P - 4; if (gr0 < 0) gr0 += LROWS;          // start row
        int n1  = SROWS; if (gr0 + n1 > LROWS) n1 = LROWS - gr0;
        int n2  = SROWS - n1;
        const char* src1 = (const char*)(vb + (size_t)gr0 * DCOLS);
        asm volatile(
            "cp.async.bulk.shared::cta.global.mbarrier::complete_tx::bytes "
            "[%0], [%1], %2, [%3];"
            :: "r"(smem_base), "l"(src1), "r"((uint32_t)(n1 * ROWBYTES)),
               "r"(mbar) : "memory");
        if (n2 > 0) {
            const char* src2 = (const char*)vb;              // wrap to row 0
            asm volatile(
                "cp.async.bulk.shared::cta.global.mbarrier::complete_tx::bytes "
                "[%0], [%1], %2, [%3];"
                :: "r"(smem_base + (uint32_t)(n1 * ROWBYTES)), "l"(src2),
                   "r"((uint32_t)(n2 * ROWBYTES)), "r"(mbar) : "memory");
        }
    }

    // ---- Wait for the frame (phase 0, acquire) ----
    {
        uint32_t done;
        asm volatile(
            "{\n\t.reg .pred p;\n\t"
            "mbarrier.try_wait.parity.acquire.cta.shared::cta.b64 p, [%1], 0;\n\t"
            "selp.b32 %0, 1, 0, p;\n\t}"
            : "=r"(done) : "r"(mbar) : "memory");
        if (!done) {
            asm volatile(
                "{\n\t.reg .pred P1;\n\t"
                "WL_%=:\n\t"
                "mbarrier.try_wait.parity.acquire.cta.shared::cta.b64 P1, [%0], 0, 0x989680;\n\t"
                "@P1 bra.uni WD_%=;\n\t"
                "bra.uni WL_%=;\n\t"
                "WD_%=:\n\t}"
                :: "r"(mbar) : "memory");
        }
    }

    // ---- Sort: column tx, windows at frame rows o, o+5, o+10 (in place) ----
    // o=(c+4)%5 since P ≡ 0 (mod 5). Banks = c mod 32 -> conflict-free.
    {
        const int o = (tx + 4) % 5;
        #pragma unroll
        for (int m = 0; m < 3; m++) {
            int base = (o + 5 * m) * DCOLS + tx;
            float a0 = sm[base];
            float a1 = sm[base + 1 * DCOLS];
            float a2 = sm[base + 2 * DCOLS];
            float a3 = sm[base + 3 * DCOLS];
            float a4 = sm[base + 4 * DCOLS];
            CE(a0, a1); CE(a3, a4); CE(a2, a4);
            CE(a2, a3); CE(a0, a3); CE(a0, a2);
            CE(a1, a4); CE(a1, a3); CE(a1, a2);
            sm[base]             = a0;
            sm[base + 1 * DCOLS] = a1;
            sm[base + 2 * DCOLS] = a2;
            sm[base + 3 * DCOLS] = a3;
            sm[base + 4 * DCOLS] = a4;
        }
    }
    __syncthreads();

    // ---- Bulk-async store of frame rows [4, 14) -> out rows [P, P+10) ----
    if (tx == 0) {
        asm volatile("fence.proxy.async.shared::cta;" ::: "memory");
        char* dst = (char*)(ob + (size_t)P * DCOLS);
        asm volatile(
            "cp.async.bulk.global.shared::cta.bulk_group [%0], [%1], %2;"
            :: "l"(dst), "r"(smem_base + 4 * ROWBYTES),
               "r"((uint32_t)OUT_BYTES) : "memory");
        asm volatile("cp.async.bulk.commit_group;" ::: "memory");
        asm volatile("cp.async.bulk.wait_group 0;" ::: "memory");
    }
}

extern "C" void kernel_launch(void* const* d_in, const int* in_sizes, int n_in,
                              void* d_out, int out_size) {
    const float* v = (const float*)d_in[2];   // inputs: q (unused), k (unused), v
    float* out     = (float*)d_out;

    dim3 grid(LROWS / TROWS, 8);              // 400 x 8 = 3200 blocks
    swd_bulk_kernel<<<grid, NTHREADS, SMEM_BYTES>>>(v, out);
}